// round 17
// baseline (speedup 1.0000x reference)
#include <cuda_runtime.h>
#include <cstdint>

#define JAX_PARTITIONABLE 1

#define MAXP   (1024*2048)
#define NBMAX  512
#define ITERS  1000
#define SUBN   50000
#define CHUNK  4096          // elements per block (16 per thread)
#define NANF   0x7FC00000u

// ------------------ device scratch (self-cleaning) ------------------
__device__ int          g_bc[NBMAX];
__device__ int          g_idx[MAXP];
__device__ float        g_ymask[MAXP];          // y if mask else NaN
__device__ unsigned int g_cand[MAXP];           // compacted candidate keys
__device__ int          g_ccnt;                 // zero invariant
__device__ float        g_xsub[SUBN];
__device__ float        g_ysub[SUBN];
__device__ float        g_scales[ITERS];
__device__ float        g_shifts[ITERS];
__device__ int          g_counts[ITERS];        // zero invariant
__device__ unsigned int g_hist[6][2048];        // zero invariant
__device__ unsigned int g_done;                 // zero invariant
__device__ float        g_part[NBMAX];
__device__ volatile unsigned int g_barcnt;      // zero invariant
__device__ volatile unsigned int g_bargen;      // zero invariant (reset at end)

// ------------------ threefry2x32 (bit-exact vs JAX) ------------------
__host__ __device__ __forceinline__ void tf2x32(unsigned int k0, unsigned int k1,
                                                unsigned int x0, unsigned int x1,
                                                unsigned int& o0, unsigned int& o1) {
    unsigned int ks2 = k0 ^ k1 ^ 0x1BD11BDAu;
    x0 += k0; x1 += k1;
#define TF_RND(r) { x0 += x1; x1 = (x1 << (r)) | (x1 >> (32 - (r))); x1 ^= x0; }
    TF_RND(13) TF_RND(15) TF_RND(26) TF_RND(6)
    x0 += k1;  x1 += ks2 + 1u;
    TF_RND(17) TF_RND(29) TF_RND(16) TF_RND(24)
    x0 += ks2; x1 += k0 + 2u;
    TF_RND(13) TF_RND(15) TF_RND(26) TF_RND(6)
    x0 += k0;  x1 += k1 + 3u;
    TF_RND(17) TF_RND(29) TF_RND(16) TF_RND(24)
    x0 += k1;  x1 += ks2 + 4u;
    TF_RND(13) TF_RND(15) TF_RND(26) TF_RND(6)
    x0 += ks2; x1 += k0 + 5u;
#undef TF_RND
    o0 = x0; o1 = x1;
}

__device__ __forceinline__ unsigned int jax_bits(unsigned int ka, unsigned int kb,
                                                 unsigned int e, unsigned int n) {
#if JAX_PARTITIONABLE
    unsigned int a, b;
    tf2x32(ka, kb, 0u, e, a, b);
    return a ^ b;
#else
    unsigned int h = n >> 1;
    unsigned int lane = (e < h) ? e : (e - h);
    unsigned int a, b;
    tf2x32(ka, kb, lane, lane + h, a, b);
    return (e < h) ? a : b;
#endif
}

static inline void jax_split2_host(unsigned int ka, unsigned int kb, unsigned int* o) {
#if JAX_PARTITIONABLE
    unsigned int a, b;
    tf2x32(ka, kb, 0u, 0u, a, b); o[0] = a; o[1] = b;
    tf2x32(ka, kb, 0u, 1u, a, b); o[2] = a; o[3] = b;
#else
    unsigned int a0, b0, a1, b1;
    tf2x32(ka, kb, 0u, 2u, a0, b0);
    tf2x32(ka, kb, 1u, 3u, a1, b1);
    o[0] = a0; o[1] = a1; o[2] = b0; o[3] = b1;
#endif
}

__device__ __forceinline__ bool maskf(float d) {       // isfinite implied
    return (d > 0.1f) && (d < 100.0f);
}
__device__ __forceinline__ float y_of(float d) {
    return __fdiv_rn(1.0f, __fadd_rn(d, 1e-6f));
}
__device__ __forceinline__ unsigned int randint_off(unsigned int hb, unsigned int lb,
                                                    unsigned int span) {
    unsigned int m = 65536u % span;
    m = (m * m) % span;
    unsigned int off = (hb % span) * m + (lb % span);
    return off % span;
}
__device__ __forceinline__ float fast_rcp(float x) {   // depth output only (~1e-7)
    float r = __uint_as_float(0x7EF311C3u - __float_as_uint(x));
    r = __fmul_rn(r, __fmaf_rn(-x, r, 2.0f));
    r = __fmul_rn(r, __fmaf_rn(-x, r, 2.0f));
    r = __fmul_rn(r, __fmaf_rn(-x, r, 2.0f));
    return r;
}

// exclusive scan over 256 threads; wsh = shared int[8]
__device__ __forceinline__ int blk_scan256(int v, int* wsh) {
    int t = threadIdx.x, lane = t & 31, w = t >> 5;
    int incl = v;
#pragma unroll
    for (int off = 1; off < 32; off <<= 1) {
        int x = __shfl_up_sync(0xffffffffu, incl, off);
        if (lane >= off) incl += x;
    }
    if (lane == 31) wsh[w] = incl;
    __syncthreads();
    if (w == 0) {
        int s = (lane < 8) ? wsh[lane] : 0;
#pragma unroll
        for (int off = 1; off < 8; off <<= 1) {
            int x = __shfl_up_sync(0xffffffffu, s, off);
            if (lane >= off) s += x;
        }
        if (lane < 8) wsh[lane] = s;
    }
    __syncthreads();
    return (w ? wsh[w - 1] : 0) + incl - v;
}

// spin grid barrier; all blocks resident by construction (launch_bounds(256,4))
__device__ __forceinline__ void grid_bar(unsigned int nb) {
    __syncthreads();
    if (threadIdx.x == 0) {
        unsigned int gen = g_bargen;
        __threadfence();
        if (atomicAdd((unsigned int*)&g_barcnt, 1u) == nb - 1u) {
            g_barcnt = 0u;
            __threadfence();
            g_bargen = gen + 1u;
        } else {
            while (g_bargen == gen) __nanosleep(64);
            __threadfence();
        }
    }
    __syncthreads();
}

// redundant per-block bin selection over g_hist[hi]. L0/L1: 2048 bins, L2: 1024.
// Updates *o_rank/*o_prefix (all levels); L2 additionally writes *o_val (median value).
__device__ void choose_dev(int level, int hi, int stage, int P, int n_valid,
                           float med_in, long long r_in, unsigned int pfx_in,
                           long long* o_rank, unsigned int* o_prefix, float* o_val) {
    __shared__ int wsh[8];
    __shared__ int sh_b;
    __shared__ long long sh_e;
    __shared__ int sh_next;
    __shared__ unsigned int sh_tot;
    __shared__ int sh_need;
    __shared__ unsigned int sh_selkey, sh_vb;
    __shared__ unsigned int red[256];

    int t = threadIdx.x;
    int nb = (level == 2) ? 1024 : 2048;
    int per = nb >> 8;
    unsigned int v[8];
    int sum = 0;
#pragma unroll
    for (int j = 0; j < 8; j++) {
        v[j] = (j < per) ? g_hist[hi][t * per + j] : 0u;
        sum += (int)v[j];
    }
    if (t == 0) { sh_b = -1; sh_next = nb; }
    __syncthreads();
    int excl = blk_scan256(sum, wsh);
    if (t == 255) sh_tot = (unsigned int)(excl + sum);
    __syncthreads();
    long long r = r_in;
    if (r >= (long long)excl && r < (long long)(excl + sum)) {
        long long c = excl;
        for (int j = 0; j < per; j++) {
            if (r < c + (long long)v[j]) { sh_b = t * per + j; sh_e = c; break; }
            c += (long long)v[j];
        }
    }
    __syncthreads();
    int b = sh_b;
    if (level == 2 && b >= 0) {
        for (int j = 0; j < per; j++) {
            int idx = t * per + j;
            if (idx > b && v[j]) { atomicMin(&sh_next, idx); break; }
        }
    }
    __syncthreads();
    if (t == 0) {
        long long e = sh_e;
        int bb = b;
        long long tot = (long long)sh_tot;
        if (bb < 0) { bb = nb - 1; e = tot; }   // degenerate n==0
        long long rl = r - e;
        *o_rank = rl;
        if (level == 0) *o_prefix = (unsigned int)bb;
        else if (level == 1) *o_prefix = (pfx_in << 11) | (unsigned int)bb;
        else {
            unsigned int selkey = (pfx_in << 10) | (unsigned int)bb;
            unsigned int eq = g_hist[hi][bb];
            int need = 0;
            unsigned int vb = selkey;
            if (!(n_valid & 1)) {
                if (rl + 1 < (long long)eq) vb = selkey;
                else if (sh_next < nb)
                    vb = (pfx_in << 10) | (unsigned int)sh_next;
                else need = 1;
            }
            sh_need = need; sh_selkey = selkey; sh_vb = vb;
        }
    }
    __syncthreads();
    if (level != 2) return;

    unsigned int selkey = sh_selkey;
    unsigned int vb;
    if (sh_need) {
        // rare fallback: min key strictly greater than selkey (full ymask scan)
        unsigned int local = 0xFFFFFFFFu;
        for (int i = t; i < P; i += 256) {
            float ym = g_ymask[i];
            unsigned int kraw = __float_as_uint(ym);
            if (kraw >= 0x7F800000u) continue;
            unsigned int key = stage ? (__float_as_uint(__fsub_rn(ym, med_in)) & 0x7FFFFFFFu)
                                     : kraw;
            if (key > selkey && key < local) local = key;
        }
        red[t] = local;
        __syncthreads();
        for (int off = 128; off; off >>= 1) {
            if (t < off) red[t] = min(red[t], red[t + off]);
            __syncthreads();
        }
        vb = red[0];
    } else vb = sh_vb;

    if (t == 0) {
        float va = __uint_as_float(selkey);
        *o_val = (n_valid & 1) ? va
            : __fadd_rn(__fmul_rn(va, 0.5f), __fmul_rn(__uint_as_float(vb), 0.5f));
    }
    __syncthreads();
}

// ------------------ THE persistent kernel ------------------
__global__ void __launch_bounds__(256, 4)
k_mega(const float* __restrict__ dren, const float* __restrict__ dpri,
       float* __restrict__ yout, float* __restrict__ depth_out,
       float* __restrict__ o, int P, int NB, uint4 KP, uint4 KS) {
    __shared__ unsigned int sh[2048];
    __shared__ int wsh[8];
    __shared__ int sbc[NBMAX];
    __shared__ long long s_rank;
    __shared__ unsigned int s_prefix;
    __shared__ float s_val;
    __shared__ float shf[256];
    __shared__ double shd[256];

    int t = threadIdx.x;
    int b = blockIdx.x;
    unsigned int NBu = (unsigned int)NB;
    int s0 = b * CHUNK + t * 16;

    // ---- P0: y compute, yout+ymask stores, per-block count, L0s0 hist ----
    for (int j = t; j < 2048; j += 256) sh[j] = 0u;
    __syncthreads();
    {
        int cnt = 0;
        if (s0 + 16 <= P) {
            float4 q0 = *(const float4*)(dren + s0);
            float4 q1 = *(const float4*)(dren + s0 + 4);
            float4 q2 = *(const float4*)(dren + s0 + 8);
            float4 q3 = *(const float4*)(dren + s0 + 12);
            float dd[16] = {q0.x, q0.y, q0.z, q0.w, q1.x, q1.y, q1.z, q1.w,
                            q2.x, q2.y, q2.z, q2.w, q3.x, q3.y, q3.z, q3.w};
            float ym[16];
#pragma unroll
            for (int k = 0; k < 16; k++) {
                float y = y_of(dd[k]);
                yout[s0 + k] = y;               // scalar: dest misaligned for STG.128
                bool m = maskf(dd[k]);
                ym[k] = m ? y : __uint_as_float(NANF);
                if (m) { cnt++; atomicAdd(&sh[__float_as_uint(y) >> 21], 1u); }
            }
#pragma unroll
            for (int j = 0; j < 4; j++)
                *(float4*)(g_ymask + s0 + 4 * j) =
                    make_float4(ym[4 * j], ym[4 * j + 1], ym[4 * j + 2], ym[4 * j + 3]);
        } else {
            for (int i = s0; i < P && i < s0 + 16; i++) {
                float d = dren[i];
                float y = y_of(d);
                yout[i] = y;
                bool m = maskf(d);
                g_ymask[i] = m ? y : __uint_as_float(NANF);
                if (m) { cnt++; atomicAdd(&sh[__float_as_uint(y) >> 21], 1u); }
            }
        }
        int lane = t & 31, w = t >> 5;
        int v = cnt;
        for (int off2 = 16; off2; off2 >>= 1) v += __shfl_down_sync(0xffffffffu, v, off2);
        if (lane == 0) wsh[w] = v;
        __syncthreads();
        if (t == 0) {
            int s = 0;
            for (int j = 0; j < 8; j++) s += wsh[j];
            g_bc[b] = s;
        }
        __syncthreads();
        for (int j = t; j < 2048; j += 256)
            if (sh[j]) atomicAdd(&g_hist[0][j], sh[j]);
    }
    grid_bar(NBu);   // B1

    // ---- every block: scan g_bc redundantly; choose L0s0 ----
    int n_valid, bcoff;
    {
        int b2[2]; int s = 0;
#pragma unroll
        for (int j = 0; j < 2; j++) {
            int ii = t * 2 + j;
            b2[j] = (ii < NB) ? g_bc[ii] : 0;
            s += b2[j];
        }
        int ex = blk_scan256(s, wsh);
        int run = ex;
#pragma unroll
        for (int j = 0; j < 2; j++) {
            int ii = t * 2 + j;
            if (ii < NBMAX) sbc[ii] = run;
            run += b2[j];
        }
        if (t == 255) sbc[NBMAX - 1] = ex + s;   // placeholder overwritten below ok
        __syncthreads();
        // total: inclusive at last = recompute: thread255's run end
        // simpler: n_valid via reduce
        shf[t] = (float)0;   // unused slot; compute total by reduction on s
        __syncthreads();
        // block total:
        int v = s;
        int lane = t & 31, w = t >> 5;
        for (int off2 = 16; off2; off2 >>= 1) v += __shfl_down_sync(0xffffffffu, v, off2);
        if (lane == 0) wsh[w] = v;
        __syncthreads();
        int tot = 0;
        for (int j = 0; j < 8; j++) tot += wsh[j];
        n_valid = tot;
        bcoff = sbc[b];
    }
    bool dense = (n_valid == P);
    unsigned int span = (unsigned int)n_valid;
    long long rank0 = (n_valid > 0) ? (long long)((n_valid - 1) / 2) : 0ll;
    choose_dev(0, 0, 0, P, n_valid, 0.f, rank0, 0u, &s_rank, &s_prefix, &s_val);
    long long rank = s_rank;
    unsigned int prefix = s_prefix;

    // ---- P2: L1s0 hist + compact candidates (+ scatter if !dense) ----
    for (int j = t; j < 2048; j += 256) sh[j] = 0u;
    __syncthreads();
    {
        unsigned int key[16];
        if (s0 + 16 <= P) {
#pragma unroll
            for (int j = 0; j < 4; j++) {
                float4 a = *(const float4*)(g_ymask + s0 + 4 * j);
                key[4 * j]     = __float_as_uint(a.x);
                key[4 * j + 1] = __float_as_uint(a.y);
                key[4 * j + 2] = __float_as_uint(a.z);
                key[4 * j + 3] = __float_as_uint(a.w);
            }
        } else {
#pragma unroll
            for (int k = 0; k < 16; k++)
                key[k] = (s0 + k < P) ? __float_as_uint(g_ymask[s0 + k]) : NANF;
        }
        int nm = 0;
        unsigned int mkeys[16];
        int cnt = 0;
        unsigned int bits = 0u;
#pragma unroll
        for (int k = 0; k < 16; k++) {
            if ((key[k] >> 21) == prefix) {
                atomicAdd(&sh[(key[k] >> 10) & 2047u], 1u);
                mkeys[nm++] = key[k];
            }
            if (key[k] < 0x7F800000u) { cnt++; bits |= (1u << k); }
        }
        int mex = blk_scan256(nm, wsh);
        __shared__ int s_base, s_tot;
        if (t == 255) s_tot = mex + nm;
        __syncthreads();
        if (t == 0) s_base = atomicAdd(&g_ccnt, s_tot);
        __syncthreads();
        for (int j = 0; j < nm; j++) g_cand[s_base + mex + j] = mkeys[j];
        if (!dense) {
            int excl = blk_scan256(cnt, wsh);
            int wpos = bcoff + excl;
#pragma unroll
            for (int k = 0; k < 16; k++)
                if ((bits >> k) & 1u) g_idx[wpos++] = s0 + k;
        }
        __syncthreads();
        for (int j = t; j < 2048; j += 256)
            if (sh[j]) atomicAdd(&g_hist[1][j], sh[j]);
    }
    grid_bar(NBu);   // B2

    choose_dev(1, 1, 0, P, n_valid, 0.f, rank, prefix, &s_rank, &s_prefix, &s_val);
    rank = s_rank; prefix = s_prefix;

    // ---- P4: L2s0 hist over candidates + RANSAC sampling ----
    int ccnt = g_ccnt;
    for (int j = t; j < 1024; j += 256) sh[j] = 0u;
    __syncthreads();
    {
        int stride = NB * 256;
        int gid = b * 256 + t;
        for (int i = gid; i < ccnt; i += stride) {
            unsigned int key = g_cand[i];
            if ((key >> 10) == prefix) atomicAdd(&sh[key & 1023u], 1u);
        }
        for (int e = gid; e < SUBN; e += stride) {
            if (span == 0u) { g_xsub[e] = 0.f; g_ysub[e] = 0.f; }
            else {
                unsigned int hb = jax_bits(KS.x, KS.y, (unsigned int)e, SUBN);
                unsigned int lb = jax_bits(KS.z, KS.w, (unsigned int)e, SUBN);
                unsigned int pos = randint_off(hb, lb, span);
                int si = dense ? (int)pos : g_idx[pos];
                g_xsub[e] = dpri[si];
                g_ysub[e] = yout[si];
            }
        }
        for (int e = gid; e < ITERS; e += stride) {
            unsigned int p0 = 0u, p1 = 0u;
            if (span != 0u) {
                p0 = randint_off(jax_bits(KP.x, KP.y, 2u * e, 2u * ITERS),
                                 jax_bits(KP.z, KP.w, 2u * e, 2u * ITERS), span);
                p1 = randint_off(jax_bits(KP.x, KP.y, 2u * e + 1u, 2u * ITERS),
                                 jax_bits(KP.z, KP.w, 2u * e + 1u, 2u * ITERS), span);
            }
            int i0 = (dense && span) ? (int)p0 : g_idx[p0];
            int i1 = (dense && span) ? (int)p1 : g_idx[p1];
            float x1 = dpri[i0], x2 = dpri[i1];
            float y1 = yout[i0], y2 = yout[i1];
            float sc = __fdiv_rn(__fsub_rn(y2, y1), __fadd_rn(__fsub_rn(x2, x1), 1e-8f));
            g_scales[e] = sc;
            g_shifts[e] = __fsub_rn(y1, __fmul_rn(sc, x1));
        }
        __syncthreads();
        for (int j = t; j < 1024; j += 256)
            if (sh[j]) atomicAdd(&g_hist[2][j], sh[j]);
    }
    grid_bar(NBu);   // B3

    choose_dev(2, 2, 0, P, n_valid, 0.f, rank, prefix, &s_rank, &s_prefix, &s_val);
    float med = s_val;
    rank = (n_valid > 0) ? (long long)((n_valid - 1) / 2) : 0ll;
    if (b == 0 && t == 0) g_ccnt = 0;   // visible after B4

    // ---- P6: stage1 L0 hist (NaN -> top bin, never selected) ----
    for (int j = t; j < 2048; j += 256) sh[j] = 0u;
    __syncthreads();
    {
        if (s0 + 16 <= P) {
            float ym[16];
#pragma unroll
            for (int j = 0; j < 4; j++) {
                float4 a = *(const float4*)(g_ymask + s0 + 4 * j);
                ym[4 * j] = a.x; ym[4 * j + 1] = a.y; ym[4 * j + 2] = a.z; ym[4 * j + 3] = a.w;
            }
#pragma unroll
            for (int k = 0; k < 16; k++) {
                unsigned int key = __float_as_uint(__fsub_rn(ym[k], med)) & 0x7FFFFFFFu;
                atomicAdd(&sh[key >> 21], 1u);
            }
        } else {
            for (int i = s0; i < P && i < s0 + 16; i++) {
                unsigned int key = __float_as_uint(__fsub_rn(g_ymask[i], med)) & 0x7FFFFFFFu;
                atomicAdd(&sh[key >> 21], 1u);
            }
        }
        __syncthreads();
        for (int j = t; j < 2048; j += 256)
            if (sh[j]) atomicAdd(&g_hist[3][j], sh[j]);
    }
    grid_bar(NBu);   // B4

    choose_dev(0, 3, 1, P, n_valid, med, rank, 0u, &s_rank, &s_prefix, &s_val);
    rank = s_rank; prefix = s_prefix;

    // ---- P8: stage1 L1 hist + compact ----
    for (int j = t; j < 2048; j += 256) sh[j] = 0u;
    __syncthreads();
    {
        unsigned int key[16];
        if (s0 + 16 <= P) {
            float ym[16];
#pragma unroll
            for (int j = 0; j < 4; j++) {
                float4 a = *(const float4*)(g_ymask + s0 + 4 * j);
                ym[4 * j] = a.x; ym[4 * j + 1] = a.y; ym[4 * j + 2] = a.z; ym[4 * j + 3] = a.w;
            }
#pragma unroll
            for (int k = 0; k < 16; k++)
                key[k] = __float_as_uint(__fsub_rn(ym[k], med)) & 0x7FFFFFFFu;
        } else {
#pragma unroll
            for (int k = 0; k < 16; k++)
                key[k] = (s0 + k < P)
                    ? (__float_as_uint(__fsub_rn(g_ymask[s0 + k], med)) & 0x7FFFFFFFu)
                    : 0x7FC00000u;
        }
        int nm = 0;
        unsigned int mkeys[16];
#pragma unroll
        for (int k = 0; k < 16; k++) {
            if ((key[k] >> 21) == prefix) {
                atomicAdd(&sh[(key[k] >> 10) & 2047u], 1u);
                mkeys[nm++] = key[k];
            }
        }
        int mex = blk_scan256(nm, wsh);
        __shared__ int s_base2, s_tot2;
        if (t == 255) s_tot2 = mex + nm;
        __syncthreads();
        if (t == 0) s_base2 = atomicAdd(&g_ccnt, s_tot2);
        __syncthreads();
        for (int j = 0; j < nm; j++) g_cand[s_base2 + mex + j] = mkeys[j];
        __syncthreads();
        for (int j = t; j < 2048; j += 256)
            if (sh[j]) atomicAdd(&g_hist[4][j], sh[j]);
    }
    grid_bar(NBu);   // B5

    choose_dev(1, 4, 1, P, n_valid, med, rank, prefix, &s_rank, &s_prefix, &s_val);
    rank = s_rank; prefix = s_prefix;

    // ---- P10: stage1 L2 over candidates ----
    ccnt = g_ccnt;
    for (int j = t; j < 1024; j += 256) sh[j] = 0u;
    __syncthreads();
    {
        int stride = NB * 256;
        for (int i = b * 256 + t; i < ccnt; i += stride) {
            unsigned int key = g_cand[i];
            if ((key >> 10) == prefix) atomicAdd(&sh[key & 1023u], 1u);
        }
        __syncthreads();
        for (int j = t; j < 1024; j += 256)
            if (sh[j]) atomicAdd(&g_hist[5][j], sh[j]);
    }
    grid_bar(NBu);   // B6

    choose_dev(2, 5, 1, P, n_valid, med, rank, prefix, &s_rank, &s_prefix, &s_val);
    float dyn = __fmul_rn(s_val, 0.5f);
    if (dyn < 1e-5f) dyn = 0.01f;

    // ---- P12: RANSAC scoring (500 work units: 125 hyp-groups x 4 segments) ----
    {
        __shared__ int wc[8][8];
        for (int wb = b; wb < 500; wb += NB) {
            int hy = (wb >> 2) * 8;
            int seg = wb & 3;
            int j0 = seg * (SUBN / 4), j1 = j0 + (SUBN / 4);
            float s[8], tv[8];
            int c[8] = {0, 0, 0, 0, 0, 0, 0, 0};
#pragma unroll
            for (int k = 0; k < 8; k++) { s[k] = g_scales[hy + k]; tv[k] = g_shifts[hy + k]; }
            for (int j = j0 + t; j < j1; j += 256) {
                float x = g_xsub[j], yv = g_ysub[j];
#pragma unroll
                for (int k = 0; k < 8; k++) {
                    float r = fabsf(__fsub_rn(__fadd_rn(__fmul_rn(s[k], x), tv[k]), yv));
                    c[k] += (r < dyn) ? 1 : 0;
                }
            }
            int lane = t & 31, w = t >> 5;
#pragma unroll
            for (int k = 0; k < 8; k++) {
                int v = c[k];
                for (int off2 = 16; off2; off2 >>= 1) v += __shfl_down_sync(0xffffffffu, v, off2);
                if (lane == 0) wc[w][k] = v;
            }
            __syncthreads();
            if (t < 8) {
                int v = 0;
                for (int j = 0; j < 8; j++) v += wc[j][t];
                atomicAdd(&g_counts[hy + t], v);
            }
            __syncthreads();
        }
    }
    grid_bar(NBu);   // B7

    // ---- every block: argmax -> s,t ----
    float Sv, Tv;
    {
        __shared__ int sc[256], si[256];
        int best = -2, bidx = 0x7FFFFFFF;
        for (int i = t; i < ITERS; i += 256) {
            int cc = (g_scales[i] > 0.0f) ? g_counts[i] : -1;
            if (cc > best || (cc == best && i < bidx)) { best = cc; bidx = i; }
        }
        sc[t] = best; si[t] = bidx;
        __syncthreads();
        for (int off2 = 128; off2; off2 >>= 1) {
            if (t < off2) {
                if (sc[t + off2] > sc[t] || (sc[t + off2] == sc[t] && si[t + off2] < si[t])) {
                    sc[t] = sc[t + off2]; si[t] = si[t + off2];
                }
            }
            __syncthreads();
        }
        bool valid = sc[0] >= 0;
        Sv = valid ? g_scales[si[0]] : 1.0f;
        Tv = valid ? g_shifts[si[0]] : 0.0f;
        if (n_valid < 10) { Sv = 1.0f; Tv = 0.0f; }
        __syncthreads();
    }

    // ---- P14: outputs + loss partials ----
    {
        float acc = 0.f;
        if (s0 + 16 <= P) {
            float ym[16], pp[16];
#pragma unroll
            for (int j = 0; j < 4; j++) {
                float4 a = *(const float4*)(g_ymask + s0 + 4 * j);
                float4 p = *(const float4*)(dpri + s0 + 4 * j);
                ym[4 * j] = a.x; ym[4 * j + 1] = a.y; ym[4 * j + 2] = a.z; ym[4 * j + 3] = a.w;
                pp[4 * j] = p.x; pp[4 * j + 1] = p.y; pp[4 * j + 2] = p.z; pp[4 * j + 3] = p.w;
            }
#pragma unroll
            for (int k = 0; k < 16; k++) {
                float al = __fadd_rn(__fmul_rn(Sv, pp[k]), Tv);
                depth_out[s0 + k] = fast_rcp(fmaxf(al, 1e-4f));
                if (__float_as_uint(ym[k]) < 0x7F800000u)
                    acc += fabsf(__fsub_rn(al, ym[k]));
            }
        } else {
            for (int i = s0; i < P && i < s0 + 16; i++) {
                float al = __fadd_rn(__fmul_rn(Sv, dpri[i]), Tv);
                depth_out[i] = fast_rcp(fmaxf(al, 1e-4f));
                float ym = g_ymask[i];
                if (__float_as_uint(ym) < 0x7F800000u)
                    acc += fabsf(__fsub_rn(al, ym));
            }
        }
        shf[t] = acc;
        __syncthreads();
        for (int off2 = 128; off2; off2 >>= 1) {
            if (t < off2) shf[t] += shf[t + off2];
            __syncthreads();
        }
        if (t == 0) g_part[b] = shf[0];
    }

    // ---- last block: final loss + full cleanup ----
    __threadfence();
    __shared__ unsigned int s_last;
    if (t == 0) s_last = (atomicAdd(&g_done, 1u) == NBu - 1u) ? 1u : 0u;
    __syncthreads();
    if (!s_last) return;

    double d = 0.0;
    for (int i = t; i < NB; i += 256) d += (double)g_part[i];
    shd[t] = d;
    __syncthreads();
    for (int off2 = 128; off2; off2 >>= 1) {
        if (t < off2) shd[t] += shd[t + off2];
        __syncthreads();
    }
    if (t == 0) {
        int denom = (n_valid > 1) ? n_valid : 1;
        float l1 = (float)shd[0] / (float)denom;
        float loss = __fmul_rn(0.5f, l1);
        if (n_valid < 100) loss = 0.0f;
        o[0] = loss;
    }
    // cleanup: restore zero invariants for next graph replay
    for (int j = t; j < 6 * 2048; j += 256) ((unsigned int*)g_hist)[j] = 0u;
    for (int i = t; i < ITERS; i += 256) g_counts[i] = 0;
    if (t == 0) { g_ccnt = 0; g_done = 0u; g_barcnt = 0u; g_bargen = 0u; }
}

// ------------------ launch ------------------
extern "C" void kernel_launch(void* const* d_in, const int* in_sizes, int n_in,
                              void* d_out, int out_size) {
    const float* dren = (const float*)d_in[0];
    const float* dpri = (const float*)d_in[1];
    float* o = (float*)d_out;
    int P = in_sizes[0];
    float* yout  = o + 1;
    float* dout2 = o + 1 + P;

    unsigned int kk[4], kp[4], ks[4];
    jax_split2_host(0u, 42u, kk);
    jax_split2_host(kk[0], kk[1], kp);
    jax_split2_host(kk[2], kk[3], ks);
    uint4 KP = make_uint4(kp[0], kp[1], kp[2], kp[3]);
    uint4 KS = make_uint4(ks[0], ks[1], ks[2], ks[3]);

    int NB = (P + CHUNK - 1) / CHUNK;   // 512 for P=2M; all blocks co-resident
    k_mega<<<NB, 256>>>(dren, dpri, yout, dout2, o, P, NB, KP, KS);
}